// round 1
// baseline (speedup 1.0000x reference)
#include <cuda_runtime.h>

// Problem constants
#define S_LEN   2048
#define DM      1024
#define NHEADS  16
#define DH      64
#define BATCH   2
#define M_TOT   (BATCH * S_LEN)   // 4096 rows for all GEMMs

// ---------------------------------------------------------------------------
// Scratch (device globals; no runtime allocation allowed)
// ---------------------------------------------------------------------------
__device__ float g_qh[BATCH * NHEADS * S_LEN * DH];   // [B,H,S,Dh]
__device__ float g_kh[BATCH * NHEADS * S_LEN * DH];
__device__ float g_vh[BATCH * NHEADS * S_LEN * DH];
__device__ float g_ctx[M_TOT * DM];                   // [B,S,D] attention output

// ---------------------------------------------------------------------------
// GEMM: C[M=4096, N=1024] = A[4096,1024] @ W[1024,1024] + bias
// BM=128, BN=128, BK=16, 256 threads, 8x8 per-thread microtile.
// SEL 0/1/2: epilogue writes head-split layout into g_qh/g_kh/g_vh.
// SEL 3:     A is g_ctx, epilogue writes plain [M,N] to `outp`.
// ---------------------------------------------------------------------------
template <int SEL>
__global__ __launch_bounds__(256)
void gemm_kernel(const float* __restrict__ A,
                 const float* __restrict__ W,
                 const float* __restrict__ bias,
                 float* __restrict__ outp)
{
    __shared__ float As[16][132];   // transposed A tile, padded
    __shared__ float Bs[16][128];

    const int tid = threadIdx.x;
    const int tx  = tid & 15;       // 0..15  -> 8 output cols
    const int ty  = tid >> 4;       // 0..15  -> 8 output rows
    const int bm  = blockIdx.y;     // 0..31
    const int bn  = blockIdx.x;     // 0..7

    const float* Ap = (SEL == 3) ? g_ctx : A;
    const float* Ablk = Ap + (size_t)bm * 128 * DM;
    const float* Wblk = W + bn * 128;

    float acc[8][8];
#pragma unroll
    for (int i = 0; i < 8; i++)
#pragma unroll
        for (int j = 0; j < 8; j++) acc[i][j] = 0.f;

    for (int kt = 0; kt < DM; kt += 16) {
        // Load A tile (128x16), store transposed As[k][m]
#pragma unroll
        for (int it = 0; it < 2; it++) {
            int id  = tid + it * 256;          // 0..511
            int row = id >> 2;                 // 0..127
            int kq  = (id & 3) * 4;            // 0,4,8,12
            float4 v = *(const float4*)(Ablk + (size_t)row * DM + kt + kq);
            As[kq + 0][row] = v.x;
            As[kq + 1][row] = v.y;
            As[kq + 2][row] = v.z;
            As[kq + 3][row] = v.w;
        }
        // Load B tile (16x128) direct
#pragma unroll
        for (int it = 0; it < 2; it++) {
            int id  = tid + it * 256;          // 0..511
            int row = id >> 5;                 // 0..15
            int cq  = (id & 31) * 4;           // 0..124
            *(float4*)(&Bs[row][cq]) =
                *(const float4*)(Wblk + (size_t)(kt + row) * DM + cq);
        }
        __syncthreads();

#pragma unroll
        for (int k = 0; k < 16; k++) {
            float4 a0 = *(const float4*)(&As[k][ty * 8]);
            float4 a1 = *(const float4*)(&As[k][ty * 8 + 4]);
            float4 b0 = *(const float4*)(&Bs[k][tx * 8]);
            float4 b1 = *(const float4*)(&Bs[k][tx * 8 + 4]);
            float a[8] = {a0.x, a0.y, a0.z, a0.w, a1.x, a1.y, a1.z, a1.w};
            float b[8] = {b0.x, b0.y, b0.z, b0.w, b1.x, b1.y, b1.z, b1.w};
#pragma unroll
            for (int i = 0; i < 8; i++)
#pragma unroll
                for (int j = 0; j < 8; j++)
                    acc[i][j] = fmaf(a[i], b[j], acc[i][j]);
        }
        __syncthreads();
    }

    // Epilogue
#pragma unroll
    for (int i = 0; i < 8; i++) {
        int m = bm * 128 + ty * 8 + i;
#pragma unroll
        for (int j = 0; j < 8; j++) {
            int n = bn * 128 + tx * 8 + j;
            float val = acc[i][j] + bias[n];
            if (SEL == 3) {
                outp[(size_t)m * DM + n] = val;
            } else {
                int b = m >> 11;        // /2048
                int s = m & 2047;
                int h = n >> 6;         // /64
                int d = n & 63;
                float* dst = (SEL == 0) ? g_qh : (SEL == 1) ? g_kh : g_vh;
                dst[((size_t)(b * NHEADS + h) * S_LEN + s) * DH + d] = val;
            }
        }
    }
}

// ---------------------------------------------------------------------------
// Causal flash attention, fp32.
// grid = (S/64, B*H), block = 256 threads.
// Thread (row = tid>>2, cg = tid&3) owns one query row (of 64 in the tile)
// with a 4-thread group: 16 interleaved score columns + 16 interleaved
// output dims each. Online softmax across 64-wide K tiles.
// ---------------------------------------------------------------------------
__global__ __launch_bounds__(256)
void attn_kernel()
{
    __shared__ float Ks[64][68];
    __shared__ float Vs[64][68];
    __shared__ float Ps[64][68];   // also used to stage Q at the start

    const int tid = threadIdx.x;
    const int row = tid >> 2;      // 0..63
    const int cg  = tid & 3;       // 0..3
    const int bh  = blockIdx.y;    // 0..31
    const int q0  = blockIdx.x * 64;

    const float* Q = g_qh + (size_t)bh * S_LEN * DH;
    const float* K = g_kh + (size_t)bh * S_LEN * DH;
    const float* V = g_vh + (size_t)bh * S_LEN * DH;

    // Stage Q tile through shared (coalesced), then pull own row to registers
#pragma unroll
    for (int it = 0; it < 4; it++) {
        int id = tid + it * 256;           // 0..1023
        int r  = id >> 4;                  // 0..63
        int c4 = (id & 15) * 4;            // 0..60
        *(float4*)(&Ps[r][c4]) = *(const float4*)(Q + (size_t)(q0 + r) * DH + c4);
    }
    __syncthreads();

    float4 qv[16];
#pragma unroll
    for (int i = 0; i < 16; i++)
        qv[i] = *(const float4*)(&Ps[row][i * 4]);

    float m_r = -1e30f;
    float l_r = 0.f;
    float4 accv[4];
#pragma unroll
    for (int i = 0; i < 4; i++) accv[i] = make_float4(0.f, 0.f, 0.f, 0.f);

    const int qi = q0 + row;

    for (int k0 = 0; k0 <= q0; k0 += 64) {
        __syncthreads();   // previous tile fully consumed; Ps(Q-stage) consumed
        // Load K and V tiles (coalesced)
#pragma unroll
        for (int it = 0; it < 4; it++) {
            int id = tid + it * 256;
            int r  = id >> 4;
            int c4 = (id & 15) * 4;
            *(float4*)(&Ks[r][c4]) = *(const float4*)(K + (size_t)(k0 + r) * DH + c4);
            *(float4*)(&Vs[r][c4]) = *(const float4*)(V + (size_t)(k0 + r) * DH + c4);
        }
        __syncthreads();

        // Scores: 16 interleaved columns per thread (col = 4c + cg)
        float s[16];
#pragma unroll
        for (int c = 0; c < 16; c++) {
            int col = c * 4 + cg;
            float sum = 0.f;
#pragma unroll
            for (int kk = 0; kk < 16; kk++) {
                float4 kvv = *(const float4*)(&Ks[col][kk * 4]);
                sum = fmaf(qv[kk].x, kvv.x, sum);
                sum = fmaf(qv[kk].y, kvv.y, sum);
                sum = fmaf(qv[kk].z, kvv.z, sum);
                sum = fmaf(qv[kk].w, kvv.w, sum);
            }
            int kj = k0 + col;
            s[c] = (kj <= qi) ? sum * 0.125f : -1e30f;
        }

        // Online softmax (reduce across the 4-lane row group)
        float mt = s[0];
#pragma unroll
        for (int c = 1; c < 16; c++) mt = fmaxf(mt, s[c]);
        mt = fmaxf(mt, __shfl_xor_sync(0xffffffffu, mt, 1));
        mt = fmaxf(mt, __shfl_xor_sync(0xffffffffu, mt, 2));
        float mnew  = fmaxf(m_r, mt);
        float scale = __expf(m_r - mnew);

        float psum = 0.f;
#pragma unroll
        for (int c = 0; c < 16; c++) {
            int col = c * 4 + cg;
            float p = __expf(s[c] - mnew);
            psum += p;
            Ps[row][col] = p;
        }
        psum += __shfl_xor_sync(0xffffffffu, psum, 1);
        psum += __shfl_xor_sync(0xffffffffu, psum, 2);
        l_r = l_r * scale + psum;
        m_r = mnew;
#pragma unroll
        for (int i = 0; i < 4; i++) {
            accv[i].x *= scale; accv[i].y *= scale;
            accv[i].z *= scale; accv[i].w *= scale;
        }
        __syncwarp();   // Ps row written by same-warp lanes only

        // PV accumulate: dims chunk (4i+cg)*4 per thread
#pragma unroll
        for (int j = 0; j < 64; j++) {
            float p = Ps[row][j];
#pragma unroll
            for (int i = 0; i < 4; i++) {
                float4 vv = *(const float4*)(&Vs[j][(4 * i + cg) * 4]);
                accv[i].x = fmaf(p, vv.x, accv[i].x);
                accv[i].y = fmaf(p, vv.y, accv[i].y);
                accv[i].z = fmaf(p, vv.z, accv[i].z);
                accv[i].w = fmaf(p, vv.w, accv[i].w);
            }
        }
    }

    // Epilogue: normalize and write ctx in [B,S,D] layout
    float inv = 1.f / l_r;
    int b = bh >> 4;
    int h = bh & 15;
    float* dst = g_ctx + ((size_t)(b * S_LEN + qi) * DM) + h * DH;
#pragma unroll
    for (int i = 0; i < 4; i++) {
        float4 o;
        o.x = accv[i].x * inv; o.y = accv[i].y * inv;
        o.z = accv[i].z * inv; o.w = accv[i].w * inv;
        *(float4*)(dst + (4 * i + cg) * 4) = o;
    }
}

// ---------------------------------------------------------------------------
// Launch
// Inputs (metadata order): q,k,v,mask,w_q,b_q,w_k,b_k,w_v,b_v,w_o,b_o
// mask is the fixed causal tril -> handled analytically in attn_kernel.
// ---------------------------------------------------------------------------
extern "C" void kernel_launch(void* const* d_in, const int* in_sizes, int n_in,
                              void* d_out, int out_size)
{
    const float* q   = (const float*)d_in[0];
    const float* k   = (const float*)d_in[1];
    const float* v   = (const float*)d_in[2];
    const float* w_q = (const float*)d_in[4];
    const float* b_q = (const float*)d_in[5];
    const float* w_k = (const float*)d_in[6];
    const float* b_k = (const float*)d_in[7];
    const float* w_v = (const float*)d_in[8];
    const float* b_v = (const float*)d_in[9];
    const float* w_o = (const float*)d_in[10];
    const float* b_o = (const float*)d_in[11];
    float* out = (float*)d_out;

    dim3 ggrid(8, 32);
    dim3 gblk(256);

    gemm_kernel<0><<<ggrid, gblk>>>(q, w_q, b_q, nullptr);
    gemm_kernel<1><<<ggrid, gblk>>>(k, w_k, b_k, nullptr);
    gemm_kernel<2><<<ggrid, gblk>>>(v, w_v, b_v, nullptr);

    dim3 agrid(S_LEN / 64, BATCH * NHEADS);
    attn_kernel<<<agrid, gblk>>>();

    gemm_kernel<3><<<ggrid, gblk>>>(nullptr, w_o, b_o, out);
}

// round 3
// speedup vs baseline: 1.2580x; 1.2580x over previous
#include <cuda_runtime.h>
#include <cuda_bf16.h>
#include <cstdint>

// Problem constants
#define S_LEN   2048
#define DM      1024
#define NHEADS  16
#define DH      64
#define BATCH   2
#define M_TOT   (BATCH * S_LEN)   // 4096

// ---------------------------------------------------------------------------
// Scratch (device globals)
// ---------------------------------------------------------------------------
__device__ float g_qh[BATCH * NHEADS * S_LEN * DH];   // [B,H,S,Dh]
__device__ float g_kh[BATCH * NHEADS * S_LEN * DH];
__device__ float g_vh[BATCH * NHEADS * S_LEN * DH];
__device__ __nv_bfloat16 g_ahi[M_TOT * DM];           // activation hi (bf16)
__device__ __nv_bfloat16 g_alo[M_TOT * DM];           // activation lo (bf16)
__device__ __nv_bfloat16 g_whi[DM * DM];              // W^T hi (bf16), [N,K]
__device__ __nv_bfloat16 g_wlo[DM * DM];              // W^T lo (bf16), [N,K]

// ---------------------------------------------------------------------------
// Helpers
// ---------------------------------------------------------------------------
__device__ __forceinline__ uint32_t smem_to_u32(const void* p) {
    uint32_t a;
    asm("{ .reg .u64 t; cvta.to.shared.u64 t, %1; cvt.u32.u64 %0, t; }"
        : "=r"(a) : "l"(p));
    return a;
}

__device__ __forceinline__ void ldsm4(uint32_t& r0, uint32_t& r1,
                                      uint32_t& r2, uint32_t& r3, uint32_t addr) {
    asm volatile("ldmatrix.sync.aligned.m8n8.x4.shared.b16 {%0,%1,%2,%3}, [%4];"
                 : "=r"(r0), "=r"(r1), "=r"(r2), "=r"(r3) : "r"(addr));
}

__device__ __forceinline__ void mma16816(float* d, const uint32_t* a,
                                         uint32_t b0, uint32_t b1) {
    asm volatile(
        "mma.sync.aligned.m16n8k16.row.col.f32.bf16.bf16.f32 "
        "{%0,%1,%2,%3}, {%4,%5,%6,%7}, {%8,%9}, {%0,%1,%2,%3};"
        : "+f"(d[0]), "+f"(d[1]), "+f"(d[2]), "+f"(d[3])
        : "r"(a[0]), "r"(a[1]), "r"(a[2]), "r"(a[3]), "r"(b0), "r"(b1));
}

__device__ __forceinline__ void split_bf16(float x, __nv_bfloat16& hi, __nv_bfloat16& lo) {
    hi = __float2bfloat16(x);
    lo = __float2bfloat16(x - __bfloat162float(hi));
}

// ---------------------------------------------------------------------------
// Conversion kernels
// ---------------------------------------------------------------------------
__global__ __launch_bounds__(256)
void convert_act(const float* __restrict__ X,
                 __nv_bfloat16* __restrict__ Xhi,
                 __nv_bfloat16* __restrict__ Xlo, int n4)
{
    int i = blockIdx.x * blockDim.x + threadIdx.x;
    if (i >= n4) return;
    float4 v = ((const float4*)X)[i];
    __nv_bfloat16 h0, h1, h2, h3, l0, l1, l2, l3;
    split_bf16(v.x, h0, l0); split_bf16(v.y, h1, l1);
    split_bf16(v.z, h2, l2); split_bf16(v.w, h3, l3);
    __nv_bfloat162* ph = (__nv_bfloat162*)(Xhi + 4 * (size_t)i);
    __nv_bfloat162* pl = (__nv_bfloat162*)(Xlo + 4 * (size_t)i);
    ph[0] = __nv_bfloat162(h0, h1); ph[1] = __nv_bfloat162(h2, h3);
    pl[0] = __nv_bfloat162(l0, l1); pl[1] = __nv_bfloat162(l2, l3);
}

// fp32 W[K=1024][N=1024] -> transposed hi/lo bf16 Wt[N][K]
__global__ __launch_bounds__(256)
void convert_w(const float* __restrict__ W,
               __nv_bfloat16* __restrict__ Whi,
               __nv_bfloat16* __restrict__ Wlo)
{
    __shared__ float t[32][33];
    int bx = blockIdx.x * 32;   // n
    int by = blockIdx.y * 32;   // k
    int tx = threadIdx.x, ty = threadIdx.y;
#pragma unroll
    for (int i = ty; i < 32; i += 8)
        t[i][tx] = W[(size_t)(by + i) * DM + bx + tx];
    __syncthreads();
#pragma unroll
    for (int i = ty; i < 32; i += 8) {
        float x = t[tx][i];   // = W[by+tx][bx+i]
        __nv_bfloat16 h, l; split_bf16(x, h, l);
        size_t o = (size_t)(bx + i) * DM + by + tx;
        Whi[o] = h; Wlo[o] = l;
    }
}

// ---------------------------------------------------------------------------
// Split-bf16 GEMM via mma.sync (HMMA):
//   D[4096,1024] = A @ W^T' + bias  where A=[M,K] hi/lo bf16, W'=[N,K] hi/lo.
// Tile 128x128, BK=32. 8 warps as 4(M) x 2(N): each warp 32x64.
// MODE 0: head-split fp32 dst [B,H,S,Dh]; MODE 1: plain fp32 [M,N].
// ---------------------------------------------------------------------------
#define TP 80   // smem row pitch (bytes) for 32-bf16 rows; (5r+c)%8 perm => no LDSM conflicts

template <int MODE>
__global__ __launch_bounds__(256)
void gemm_mma(const __nv_bfloat16* __restrict__ Ahi,
              const __nv_bfloat16* __restrict__ Alo,
              const __nv_bfloat16* __restrict__ Bhi,
              const __nv_bfloat16* __restrict__ Blo,
              const float* __restrict__ bias,
              float* __restrict__ dst)
{
    __shared__ __align__(128) uint8_t sm[4][128 * TP];   // Ahi, Alo, Bhi, Blo

    const int tid   = threadIdx.x;
    const int wid   = tid >> 5;
    const int lane  = tid & 31;
    const int warpM = wid & 3;     // 0..3 -> 32-row slab
    const int warpN = wid >> 2;    // 0..1 -> 64-col slab
    const int bn    = blockIdx.x;  // 0..7
    const int bm    = blockIdx.y;  // 0..31

    const uint32_t sA0 = smem_to_u32(sm[0]);
    const uint32_t sA1 = smem_to_u32(sm[1]);
    const uint32_t sB0 = smem_to_u32(sm[2]);
    const uint32_t sB1 = smem_to_u32(sm[3]);

    const __nv_bfloat16* gAhi = Ahi + (size_t)bm * 128 * DM;
    const __nv_bfloat16* gAlo = Alo + (size_t)bm * 128 * DM;
    const __nv_bfloat16* gBhi = Bhi + (size_t)bn * 128 * DM;
    const __nv_bfloat16* gBlo = Blo + (size_t)bn * 128 * DM;

    float acc[2][8][4];
#pragma unroll
    for (int i = 0; i < 2; i++)
#pragma unroll
        for (int j = 0; j < 8; j++)
#pragma unroll
            for (int c = 0; c < 4; c++) acc[i][j][c] = 0.f;

    // ldmatrix base addresses (per-lane)
    const int lrow = lane & 15;
    const int lcol = (lane >> 4) * 16;

    for (int kt = 0; kt < DM; kt += 32) {
        // ---- load 4 tiles: 128 rows x 32 bf16 (64B) each ----
#pragma unroll
        for (int t = 0; t < 2; t++) {
            int id = tid + t * 256;        // 0..511
            int r  = id >> 2;              // 0..127
            int c  = id & 3;               // 16B chunk
            size_t go = (size_t)r * DM + kt + c * 8;
            uint32_t so = (uint32_t)(r * TP + c * 16);
            uint4 va = *(const uint4*)(gAhi + go);
            uint4 vb = *(const uint4*)(gAlo + go);
            uint4 vc = *(const uint4*)(gBhi + go);
            uint4 vd = *(const uint4*)(gBlo + go);
            *(uint4*)(sm[0] + so) = va;
            *(uint4*)(sm[1] + so) = vb;
            *(uint4*)(sm[2] + so) = vc;
            *(uint4*)(sm[3] + so) = vd;
        }
        __syncthreads();

        // ---- compute: two k16 steps ----
#pragma unroll
        for (int kk = 0; kk < 2; kk++) {
            uint32_t ah[2][4], al[2][4];
#pragma unroll
            for (int mt = 0; mt < 2; mt++) {
                uint32_t off = (uint32_t)((warpM * 32 + mt * 16 + lrow) * TP
                                          + kk * 32 + lcol);
                ldsm4(ah[mt][0], ah[mt][1], ah[mt][2], ah[mt][3], sA0 + off);
                ldsm4(al[mt][0], al[mt][1], al[mt][2], al[mt][3], sA1 + off);
            }
#pragma unroll
            for (int np = 0; np < 4; np++) {
                uint32_t off = (uint32_t)((warpN * 64 + np * 16 + lrow) * TP
                                          + kk * 32 + lcol);
                uint32_t bh0, bh1, bh2, bh3, bl0, bl1, bl2, bl3;
                ldsm4(bh0, bh1, bh2, bh3, sB0 + off);
                ldsm4(bl0, bl1, bl2, bl3, sB1 + off);
#pragma unroll
                for (int mt = 0; mt < 2; mt++) {
                    mma16816(acc[mt][2 * np],     ah[mt], bh0, bh2);  // hi*hi
                    mma16816(acc[mt][2 * np],     ah[mt], bl0, bl2);  // hi*lo
                    mma16816(acc[mt][2 * np],     al[mt], bh0, bh2);  // lo*hi
                    mma16816(acc[mt][2 * np + 1], ah[mt], bh1, bh3);
                    mma16816(acc[mt][2 * np + 1], ah[mt], bl1, bl3);
                    mma16816(acc[mt][2 * np + 1], al[mt], bh1, bh3);
                }
            }
        }
        __syncthreads();
    }

    // ---- epilogue ----
    const int qr = lane >> 2;          // 0..7
    const int qc = (lane & 3) * 2;     // 0,2,4,6
#pragma unroll
    for (int nt = 0; nt < 8; nt++) {
        int nloc = warpN * 64 + nt * 8 + qc;       // 0..127
        int n    = bn * 128 + nloc;
        float2 bb = *(const float2*)(bias + n);
#pragma unroll
        for (int mt = 0; mt < 2; mt++) {
            int m0 = bm * 128 + warpM * 32 + mt * 16 + qr;
            float2 v0, v1;
            v0.x = acc[mt][nt][0] + bb.x; v0.y = acc[mt][nt][1] + bb.y;
            v1.x = acc[mt][nt][2] + bb.x; v1.y = acc[mt][nt][3] + bb.y;
            if (MODE == 1) {
                *(float2*)(dst + (size_t)m0 * DM + n)       = v0;
                *(float2*)(dst + (size_t)(m0 + 8) * DM + n) = v1;
            } else {
                int h = n >> 6, d = n & 63;
                int b0 = m0 >> 11, s0 = m0 & 2047;
                int m1 = m0 + 8;
                int b1 = m1 >> 11, s1 = m1 & 2047;
                *(float2*)(dst + (((size_t)(b0 * NHEADS + h) * S_LEN + s0) * DH + d)) = v0;
                *(float2*)(dst + (((size_t)(b1 * NHEADS + h) * S_LEN + s1) * DH + d)) = v1;
            }
        }
    }
}

// ---------------------------------------------------------------------------
// Causal flash attention, fp32 (same math as R1 pass).
// Epilogue writes bf16 hi/lo split of ctx into g_ahi/g_alo ([B*S, D]).
// ---------------------------------------------------------------------------
__global__ __launch_bounds__(256)
void attn_kernel()
{
    __shared__ float Ks[64][68];
    __shared__ float Vs[64][68];
    __shared__ float Ps[64][68];

    const int tid = threadIdx.x;
    const int row = tid >> 2;
    const int cg  = tid & 3;
    const int bh  = blockIdx.y;
    const int q0  = blockIdx.x * 64;

    const float* Q = g_qh + (size_t)bh * S_LEN * DH;
    const float* K = g_kh + (size_t)bh * S_LEN * DH;
    const float* V = g_vh + (size_t)bh * S_LEN * DH;

#pragma unroll
    for (int it = 0; it < 4; it++) {
        int id = tid + it * 256;
        int r  = id >> 4;
        int c4 = (id & 15) * 4;
        *(float4*)(&Ps[r][c4]) = *(const float4*)(Q + (size_t)(q0 + r) * DH + c4);
    }
    __syncthreads();

    float4 qv[16];
#pragma unroll
    for (int i = 0; i < 16; i++)
        qv[i] = *(const float4*)(&Ps[row][i * 4]);

    float m_r = -1e30f;
    float l_r = 0.f;
    float4 accv[4];
#pragma unroll
    for (int i = 0; i < 4; i++) accv[i] = make_float4(0.f, 0.f, 0.f, 0.f);

    const int qi = q0 + row;

    for (int k0 = 0; k0 <= q0; k0 += 64) {
        __syncthreads();
#pragma unroll
        for (int it = 0; it < 4; it++) {
            int id = tid + it * 256;
            int r  = id >> 4;
            int c4 = (id & 15) * 4;
            *(float4*)(&Ks[r][c4]) = *(const float4*)(K + (size_t)(k0 + r) * DH + c4);
            *(float4*)(&Vs[r][c4]) = *(const float4*)(V + (size_t)(k0 + r) * DH + c4);
        }
        __syncthreads();

        float s[16];
#pragma unroll
        for (int c = 0; c < 16; c++) {
            int col = c * 4 + cg;
            float sum = 0.f;
#pragma unroll
            for (int kk = 0; kk < 16; kk++) {
                float4 kvv = *(const float4*)(&Ks[col][kk * 4]);
                sum = fmaf(qv[kk].x, kvv.x, sum);
                sum = fmaf(qv[kk].y, kvv.y, sum);
                sum = fmaf(qv[kk].z, kvv.z, sum);
                sum = fmaf(qv[kk].w, kvv.w, sum);
            }
            int kj = k0 + col;
            s[c] = (kj <= qi) ? sum * 0.125f : -1e30f;
        }

        float mt = s[0];
#pragma unroll
        for (int c = 1; c < 16; c++) mt = fmaxf(mt, s[c]);
        mt = fmaxf(mt, __shfl_xor_sync(0xffffffffu, mt, 1));
        mt = fmaxf(mt, __shfl_xor_sync(0xffffffffu, mt, 2));
        float mnew  = fmaxf(m_r, mt);
        float scale = __expf(m_r - mnew);

        float psum = 0.f;
#pragma unroll
        for (int c = 0; c < 16; c++) {
            int col = c * 4 + cg;
            float p = __expf(s[c] - mnew);
            psum += p;
            Ps[row][col] = p;
        }
        psum += __shfl_xor_sync(0xffffffffu, psum, 1);
        psum += __shfl_xor_sync(0xffffffffu, psum, 2);
        l_r = l_r * scale + psum;
        m_r = mnew;
#pragma unroll
        for (int i = 0; i < 4; i++) {
            accv[i].x *= scale; accv[i].y *= scale;
            accv[i].z *= scale; accv[i].w *= scale;
        }
        __syncwarp();

#pragma unroll
        for (int j = 0; j < 64; j++) {
            float p = Ps[row][j];
#pragma unroll
            for (int i = 0; i < 4; i++) {
                float4 vv = *(const float4*)(&Vs[j][(4 * i + cg) * 4]);
                accv[i].x = fmaf(p, vv.x, accv[i].x);
                accv[i].y = fmaf(p, vv.y, accv[i].y);
                accv[i].z = fmaf(p, vv.z, accv[i].z);
                accv[i].w = fmaf(p, vv.w, accv[i].w);
            }
        }
    }

    float inv = 1.f / l_r;
    int b = bh >> 4;
    int h = bh & 15;
    size_t rowbase = ((size_t)(b * S_LEN + qi) * DM) + h * DH;
#pragma unroll
    for (int i = 0; i < 4; i++) {
        float o0 = accv[i].x * inv, o1 = accv[i].y * inv;
        float o2 = accv[i].z * inv, o3 = accv[i].w * inv;
        __nv_bfloat16 h0, h1, h2, h3, l0, l1, l2, l3;
        split_bf16(o0, h0, l0); split_bf16(o1, h1, l1);
        split_bf16(o2, h2, l2); split_bf16(o3, h3, l3);
        size_t off = rowbase + (4 * i + cg) * 4;
        __nv_bfloat162* ph = (__nv_bfloat162*)(g_ahi + off);
        __nv_bfloat162* pl = (__nv_bfloat162*)(g_alo + off);
        ph[0] = __nv_bfloat162(h0, h1); ph[1] = __nv_bfloat162(h2, h3);
        pl[0] = __nv_bfloat162(l0, l1); pl[1] = __nv_bfloat162(l2, l3);
    }
}

// ---------------------------------------------------------------------------
// Launch. Inputs: q,k,v,mask,w_q,b_q,w_k,b_k,w_v,b_v,w_o,b_o
// ---------------------------------------------------------------------------
extern "C" void kernel_launch(void* const* d_in, const int* in_sizes, int n_in,
                              void* d_out, int out_size)
{
    const float* q   = (const float*)d_in[0];
    const float* k   = (const float*)d_in[1];
    const float* v   = (const float*)d_in[2];
    const float* w_q = (const float*)d_in[4];
    const float* b_q = (const float*)d_in[5];
    const float* w_k = (const float*)d_in[6];
    const float* b_k = (const float*)d_in[7];
    const float* w_v = (const float*)d_in[8];
    const float* b_v = (const float*)d_in[9];
    const float* w_o = (const float*)d_in[10];
    const float* b_o = (const float*)d_in[11];
    float* out = (float*)d_out;

    __nv_bfloat16 *ahi, *alo, *whi, *wlo;
    float *qh, *kh, *vh;
    cudaGetSymbolAddress((void**)&ahi, g_ahi);
    cudaGetSymbolAddress((void**)&alo, g_alo);
    cudaGetSymbolAddress((void**)&whi, g_whi);
    cudaGetSymbolAddress((void**)&wlo, g_wlo);
    cudaGetSymbolAddress((void**)&qh, g_qh);
    cudaGetSymbolAddress((void**)&kh, g_kh);
    cudaGetSymbolAddress((void**)&vh, g_vh);

    dim3 wgrid(32, 32), wblk(32, 8);
    dim3 ggrid(8, 32),  gblk(256);
    const int n4 = M_TOT * DM / 4;

    // Q projection
    convert_w<<<wgrid, wblk>>>(w_q, whi, wlo);
    convert_act<<<(n4 + 255) / 256, 256>>>(q, ahi, alo, n4);
    gemm_mma<0><<<ggrid, gblk>>>(ahi, alo, whi, wlo, b_q, qh);
    // K projection
    convert_w<<<wgrid, wblk>>>(w_k, whi, wlo);
    convert_act<<<(n4 + 255) / 256, 256>>>(k, ahi, alo, n4);
    gemm_mma<0><<<ggrid, gblk>>>(ahi, alo, whi, wlo, b_k, kh);
    // V projection
    convert_w<<<wgrid, wblk>>>(w_v, whi, wlo);
    convert_act<<<(n4 + 255) / 256, 256>>>(v, ahi, alo, n4);
    gemm_mma<0><<<ggrid, gblk>>>(ahi, alo, whi, wlo, b_v, vh);

    // Attention (writes ctx split into g_ahi/g_alo)
    dim3 agrid(S_LEN / 64, BATCH * NHEADS);
    attn_kernel<<<agrid, 256>>>();

    // Output projection
    convert_w<<<wgrid, wblk>>>(w_o, whi, wlo);
    gemm_mma<1><<<ggrid, gblk>>>(ahi, alo, whi, wlo, b_o, out);
}

// round 4
// speedup vs baseline: 2.7833x; 2.2125x over previous
#include <cuda_runtime.h>
#include <cuda_bf16.h>
#include <cstdint>

#define S_LEN   2048
#define DM      1024
#define NHEADS  16
#define DH      64
#define BATCH   2
#define M_TOT   (BATCH * S_LEN)   // 4096

// ---------------------------------------------------------------------------
// Scratch (device globals)
// ---------------------------------------------------------------------------
__device__ __nv_bfloat16 g_qhh[BATCH * NHEADS * S_LEN * DH];  // Q heads hi
__device__ __nv_bfloat16 g_qhl[BATCH * NHEADS * S_LEN * DH];  // Q heads lo
__device__ __nv_bfloat16 g_khh[BATCH * NHEADS * S_LEN * DH];
__device__ __nv_bfloat16 g_khl[BATCH * NHEADS * S_LEN * DH];
__device__ __nv_bfloat16 g_vhh[BATCH * NHEADS * S_LEN * DH];
__device__ __nv_bfloat16 g_vhl[BATCH * NHEADS * S_LEN * DH];
__device__ __nv_bfloat16 g_ahi[M_TOT * DM];                   // GEMM act hi
__device__ __nv_bfloat16 g_alo[M_TOT * DM];                   // GEMM act lo
__device__ __nv_bfloat16 g_whi[DM * DM];                      // W^T hi [N,K]
__device__ __nv_bfloat16 g_wlo[DM * DM];                      // W^T lo [N,K]

// ---------------------------------------------------------------------------
// Helpers
// ---------------------------------------------------------------------------
__device__ __forceinline__ uint32_t smem_to_u32(const void* p) {
    uint32_t a;
    asm("{ .reg .u64 t; cvta.to.shared.u64 t, %1; cvt.u32.u64 %0, t; }"
        : "=r"(a) : "l"(p));
    return a;
}
__device__ __forceinline__ void ldsm4(uint32_t& r0, uint32_t& r1,
                                      uint32_t& r2, uint32_t& r3, uint32_t a) {
    asm volatile("ldmatrix.sync.aligned.m8n8.x4.shared.b16 {%0,%1,%2,%3}, [%4];"
                 : "=r"(r0), "=r"(r1), "=r"(r2), "=r"(r3) : "r"(a));
}
__device__ __forceinline__ void ldsm4t(uint32_t& r0, uint32_t& r1,
                                       uint32_t& r2, uint32_t& r3, uint32_t a) {
    asm volatile("ldmatrix.sync.aligned.m8n8.x4.trans.shared.b16 {%0,%1,%2,%3}, [%4];"
                 : "=r"(r0), "=r"(r1), "=r"(r2), "=r"(r3) : "r"(a));
}
__device__ __forceinline__ void mma16816(float* d, const uint32_t* a,
                                         uint32_t b0, uint32_t b1) {
    asm volatile(
        "mma.sync.aligned.m16n8k16.row.col.f32.bf16.bf16.f32 "
        "{%0,%1,%2,%3}, {%4,%5,%6,%7}, {%8,%9}, {%0,%1,%2,%3};"
        : "+f"(d[0]), "+f"(d[1]), "+f"(d[2]), "+f"(d[3])
        : "r"(a[0]), "r"(a[1]), "r"(a[2]), "r"(a[3]), "r"(b0), "r"(b1));
}
__device__ __forceinline__ void split_bf16(float x, __nv_bfloat16& hi, __nv_bfloat16& lo) {
    hi = __float2bfloat16(x);
    lo = __float2bfloat16(x - __bfloat162float(hi));
}
// pack (a,b) -> bf16x2 hi reg + residual lo reg
__device__ __forceinline__ void split_pack2(float a, float b, uint32_t& hi, uint32_t& lo) {
    __nv_bfloat162 h = __floats2bfloat162_rn(a, b);
    hi = *(uint32_t*)&h;
    float2 f = __bfloat1622float2(h);
    __nv_bfloat162 l = __floats2bfloat162_rn(a - f.x, b - f.y);
    lo = *(uint32_t*)&l;
}

// ---------------------------------------------------------------------------
// Conversion kernels
// ---------------------------------------------------------------------------
__global__ __launch_bounds__(256)
void convert_act(const float* __restrict__ X,
                 __nv_bfloat16* __restrict__ Xhi,
                 __nv_bfloat16* __restrict__ Xlo, int n4)
{
    int i = blockIdx.x * blockDim.x + threadIdx.x;
    if (i >= n4) return;
    float4 v = ((const float4*)X)[i];
    __nv_bfloat16 h0, h1, h2, h3, l0, l1, l2, l3;
    split_bf16(v.x, h0, l0); split_bf16(v.y, h1, l1);
    split_bf16(v.z, h2, l2); split_bf16(v.w, h3, l3);
    __nv_bfloat162* ph = (__nv_bfloat162*)(Xhi + 4 * (size_t)i);
    __nv_bfloat162* pl = (__nv_bfloat162*)(Xlo + 4 * (size_t)i);
    ph[0] = __nv_bfloat162(h0, h1); ph[1] = __nv_bfloat162(h2, h3);
    pl[0] = __nv_bfloat162(l0, l1); pl[1] = __nv_bfloat162(l2, l3);
}

__global__ __launch_bounds__(256)
void convert_w(const float* __restrict__ W,
               __nv_bfloat16* __restrict__ Whi,
               __nv_bfloat16* __restrict__ Wlo)
{
    __shared__ float t[32][33];
    int bx = blockIdx.x * 32;   // n
    int by = blockIdx.y * 32;   // k
    int tx = threadIdx.x, ty = threadIdx.y;
#pragma unroll
    for (int i = ty; i < 32; i += 8)
        t[i][tx] = W[(size_t)(by + i) * DM + bx + tx];
    __syncthreads();
#pragma unroll
    for (int i = ty; i < 32; i += 8) {
        float x = t[tx][i];
        __nv_bfloat16 h, l; split_bf16(x, h, l);
        size_t o = (size_t)(bx + i) * DM + by + tx;
        Whi[o] = h; Wlo[o] = l;
    }
}

// ---------------------------------------------------------------------------
// Split-bf16 GEMM via mma.sync. Tile 128x128, BK=32, 8 warps (4M x 2N).
// MODE 0: dst = head-split bf16 hi/lo [B,H,S,Dh] (QKV projections)
// MODE 1: dst = plain fp32 [M,N]              (output projection)
// ---------------------------------------------------------------------------
#define TP 80

template <int MODE>
__global__ __launch_bounds__(256)
void gemm_mma(const __nv_bfloat16* __restrict__ Ahi,
              const __nv_bfloat16* __restrict__ Alo,
              const __nv_bfloat16* __restrict__ Bhi,
              const __nv_bfloat16* __restrict__ Blo,
              const float* __restrict__ bias,
              float* __restrict__ dstF,
              __nv_bfloat16* __restrict__ dstHi,
              __nv_bfloat16* __restrict__ dstLo)
{
    __shared__ __align__(128) uint8_t sm[4][128 * TP];

    const int tid   = threadIdx.x;
    const int wid   = tid >> 5;
    const int lane  = tid & 31;
    const int warpM = wid & 3;
    const int warpN = wid >> 2;
    const int bn    = blockIdx.x;
    const int bm    = blockIdx.y;

    const uint32_t sA0 = smem_to_u32(sm[0]);
    const uint32_t sA1 = smem_to_u32(sm[1]);
    const uint32_t sB0 = smem_to_u32(sm[2]);
    const uint32_t sB1 = smem_to_u32(sm[3]);

    const __nv_bfloat16* gAhi = Ahi + (size_t)bm * 128 * DM;
    const __nv_bfloat16* gAlo = Alo + (size_t)bm * 128 * DM;
    const __nv_bfloat16* gBhi = Bhi + (size_t)bn * 128 * DM;
    const __nv_bfloat16* gBlo = Blo + (size_t)bn * 128 * DM;

    float acc[2][8][4];
#pragma unroll
    for (int i = 0; i < 2; i++)
#pragma unroll
        for (int j = 0; j < 8; j++)
#pragma unroll
            for (int c = 0; c < 4; c++) acc[i][j][c] = 0.f;

    const int lrow = lane & 15;
    const int lcol = (lane >> 4) * 16;

    for (int kt = 0; kt < DM; kt += 32) {
#pragma unroll
        for (int t = 0; t < 2; t++) {
            int id = tid + t * 256;
            int r  = id >> 2;
            int c  = id & 3;
            size_t go = (size_t)r * DM + kt + c * 8;
            uint32_t so = (uint32_t)(r * TP + c * 16);
            uint4 va = *(const uint4*)(gAhi + go);
            uint4 vb = *(const uint4*)(gAlo + go);
            uint4 vc = *(const uint4*)(gBhi + go);
            uint4 vd = *(const uint4*)(gBlo + go);
            *(uint4*)(sm[0] + so) = va;
            *(uint4*)(sm[1] + so) = vb;
            *(uint4*)(sm[2] + so) = vc;
            *(uint4*)(sm[3] + so) = vd;
        }
        __syncthreads();

#pragma unroll
        for (int kk = 0; kk < 2; kk++) {
            uint32_t ah[2][4], al[2][4];
#pragma unroll
            for (int mt = 0; mt < 2; mt++) {
                uint32_t off = (uint32_t)((warpM * 32 + mt * 16 + lrow) * TP
                                          + kk * 32 + lcol);
                ldsm4(ah[mt][0], ah[mt][1], ah[mt][2], ah[mt][3], sA0 + off);
                ldsm4(al[mt][0], al[mt][1], al[mt][2], al[mt][3], sA1 + off);
            }
#pragma unroll
            for (int np = 0; np < 4; np++) {
                uint32_t off = (uint32_t)((warpN * 64 + np * 16 + lrow) * TP
                                          + kk * 32 + lcol);
                uint32_t bh0, bh1, bh2, bh3, bl0, bl1, bl2, bl3;
                ldsm4(bh0, bh1, bh2, bh3, sB0 + off);
                ldsm4(bl0, bl1, bl2, bl3, sB1 + off);
#pragma unroll
                for (int mt = 0; mt < 2; mt++) {
                    mma16816(acc[mt][2 * np],     ah[mt], bh0, bh2);
                    mma16816(acc[mt][2 * np],     ah[mt], bl0, bl2);
                    mma16816(acc[mt][2 * np],     al[mt], bh0, bh2);
                    mma16816(acc[mt][2 * np + 1], ah[mt], bh1, bh3);
                    mma16816(acc[mt][2 * np + 1], ah[mt], bl1, bl3);
                    mma16816(acc[mt][2 * np + 1], al[mt], bh1, bh3);
                }
            }
        }
        __syncthreads();
    }

    const int qr = lane >> 2;
    const int qc = (lane & 3) * 2;
#pragma unroll
    for (int nt = 0; nt < 8; nt++) {
        int n = bn * 128 + warpN * 64 + nt * 8 + qc;
        float2 bb = *(const float2*)(bias + n);
#pragma unroll
        for (int mt = 0; mt < 2; mt++) {
            int m0 = bm * 128 + warpM * 32 + mt * 16 + qr;
            float v00 = acc[mt][nt][0] + bb.x, v01 = acc[mt][nt][1] + bb.y;
            float v10 = acc[mt][nt][2] + bb.x, v11 = acc[mt][nt][3] + bb.y;
            if (MODE == 1) {
                *(float2*)(dstF + (size_t)m0 * DM + n)       = make_float2(v00, v01);
                *(float2*)(dstF + (size_t)(m0 + 8) * DM + n) = make_float2(v10, v11);
            } else {
                int h = n >> 6, d = n & 63;
                int b0 = m0 >> 11, s0 = m0 & 2047;
                int m1 = m0 + 8;
                int b1 = m1 >> 11, s1 = m1 & 2047;
                size_t o0 = ((size_t)(b0 * NHEADS + h) * S_LEN + s0) * DH + d;
                size_t o1 = ((size_t)(b1 * NHEADS + h) * S_LEN + s1) * DH + d;
                uint32_t h2, l2;
                split_pack2(v00, v01, h2, l2);
                *(uint32_t*)(dstHi + o0) = h2; *(uint32_t*)(dstLo + o0) = l2;
                split_pack2(v10, v11, h2, l2);
                *(uint32_t*)(dstHi + o1) = h2; *(uint32_t*)(dstLo + o1) = l2;
            }
        }
    }
}

// ---------------------------------------------------------------------------
// Tensor-core causal flash attention.
// grid = (32 qtiles, 32 bh), block = 128 (4 warps; warp w -> 16 q rows).
// Q/K/V operands: bf16 hi/lo split. Scores and PV as 3-term split MMAs.
// Output: bf16 hi/lo split ctx into g_ahi/g_alo [B*S, DM].
// ---------------------------------------------------------------------------
// swizzled smem tile: 64 rows x 64 bf16 (128B rows); chunk c of row r at c^(r&7)
#define TILE_OFF(r, c) ((uint32_t)((r) * 128 + (((c) ^ ((r) & 7)) << 4)))

__global__ __launch_bounds__(128)
void attn_mma()
{
    __shared__ __align__(128) uint8_t sq[2][8192];
    __shared__ __align__(128) uint8_t sk[2][8192];
    __shared__ __align__(128) uint8_t sv[2][8192];

    const int tid  = threadIdx.x;
    const int wid  = tid >> 5;
    const int lane = tid & 31;
    const int bh   = blockIdx.y;
    const int qt   = gridDim.x - 1 - blockIdx.x;   // heavy tiles first
    const int q0   = qt * 64;

    const size_t hb = (size_t)bh * S_LEN * DH;
    const __nv_bfloat16* Qh = g_qhh + hb;
    const __nv_bfloat16* Ql = g_qhl + hb;
    const __nv_bfloat16* Kh = g_khh + hb;
    const __nv_bfloat16* Kl = g_khl + hb;
    const __nv_bfloat16* Vh = g_vhh + hb;
    const __nv_bfloat16* Vl = g_vhl + hb;

    const uint32_t sq0 = smem_to_u32(sq[0]), sq1 = smem_to_u32(sq[1]);
    const uint32_t sk0 = smem_to_u32(sk[0]), sk1 = smem_to_u32(sk[1]);
    const uint32_t sv0 = smem_to_u32(sv[0]), sv1 = smem_to_u32(sv[1]);

    // ---- stage Q tile ----
#pragma unroll
    for (int it = 0; it < 4; it++) {
        int id = tid + it * 128;      // 0..511
        int r  = id >> 3;             // 0..63
        int c  = id & 7;
        uint32_t so = TILE_OFF(r, c);
        size_t  go = (size_t)(q0 + r) * DH + c * 8;
        *(uint4*)(sq[0] + so) = *(const uint4*)(Qh + go);
        *(uint4*)(sq[1] + so) = *(const uint4*)(Ql + go);
    }
    __syncthreads();

    // ---- Q fragments (per warp, 16 rows), 4 k-steps ----
    const int lrow = lane & 15;
    const int lsel = lane >> 4;
    uint32_t qfh[4][4], qfl[4][4];
    {
        int r = wid * 16 + lrow;
#pragma unroll
        for (int ks = 0; ks < 4; ks++) {
            uint32_t off = TILE_OFF(r, ks * 2 + lsel);
            ldsm4(qfh[ks][0], qfh[ks][1], qfh[ks][2], qfh[ks][3], sq0 + off);
            ldsm4(qfl[ks][0], qfl[ks][1], qfl[ks][2], qfl[ks][3], sq1 + off);
        }
    }

    float m0 = -1e30f, m1 = -1e30f, l0 = 0.f, l1 = 0.f;
    float acc[8][4];
#pragma unroll
    for (int n = 0; n < 8; n++)
#pragma unroll
        for (int c = 0; c < 4; c++) acc[n][c] = 0.f;

    const int gr  = lane >> 2;
    const int gc2 = (lane & 3) * 2;
    const int qi0 = q0 + wid * 16 + gr;
    const int qi1 = qi0 + 8;

    for (int k0 = 0; k0 <= q0; k0 += 64) {
        __syncthreads();
        // stage K,V tiles
#pragma unroll
        for (int it = 0; it < 4; it++) {
            int id = tid + it * 128;
            int r  = id >> 3;
            int c  = id & 7;
            uint32_t so = TILE_OFF(r, c);
            size_t  go = (size_t)(k0 + r) * DH + c * 8;
            uint4 a = *(const uint4*)(Kh + go);
            uint4 b = *(const uint4*)(Kl + go);
            uint4 cc = *(const uint4*)(Vh + go);
            uint4 d = *(const uint4*)(Vl + go);
            *(uint4*)(sk[0] + so) = a;
            *(uint4*)(sk[1] + so) = b;
            *(uint4*)(sv[0] + so) = cc;
            *(uint4*)(sv[1] + so) = d;
        }
        __syncthreads();

        // ---- scores S = Q K^T ----
        float sc[8][4];
#pragma unroll
        for (int n = 0; n < 8; n++)
#pragma unroll
            for (int c = 0; c < 4; c++) sc[n][c] = 0.f;

#pragma unroll
        for (int np = 0; np < 4; np++) {
            int r = np * 16 + lrow;
#pragma unroll
            for (int ks = 0; ks < 4; ks++) {
                uint32_t off = TILE_OFF(r, ks * 2 + lsel);
                uint32_t kh0, kh1, kh2, kh3, kl0, kl1, kl2, kl3;
                ldsm4(kh0, kh1, kh2, kh3, sk0 + off);
                ldsm4(kl0, kl1, kl2, kl3, sk1 + off);
                mma16816(sc[2 * np],     qfh[ks], kh0, kh2);
                mma16816(sc[2 * np],     qfh[ks], kl0, kl2);
                mma16816(sc[2 * np],     qfl[ks], kh0, kh2);
                mma16816(sc[2 * np + 1], qfh[ks], kh1, kh3);
                mma16816(sc[2 * np + 1], qfh[ks], kl1, kl3);
                mma16816(sc[2 * np + 1], qfl[ks], kh1, kh3);
            }
        }

        // ---- scale + causal mask ----
#pragma unroll
        for (int n = 0; n < 8; n++) {
            int cb = k0 + n * 8 + gc2;
#pragma unroll
            for (int c = 0; c < 4; c++) {
                int col = cb + (c & 1);
                int row = (c < 2) ? qi0 : qi1;
                float v = sc[n][c] * 0.125f;
                sc[n][c] = (col <= row) ? v : -1e30f;
            }
        }

        // ---- online softmax ----
        float mx0 = -1e30f, mx1 = -1e30f;
#pragma unroll
        for (int n = 0; n < 8; n++) {
            mx0 = fmaxf(mx0, fmaxf(sc[n][0], sc[n][1]));
            mx1 = fmaxf(mx1, fmaxf(sc[n][2], sc[n][3]));
        }
        mx0 = fmaxf(mx0, __shfl_xor_sync(0xffffffffu, mx0, 1));
        mx0 = fmaxf(mx0, __shfl_xor_sync(0xffffffffu, mx0, 2));
        mx1 = fmaxf(mx1, __shfl_xor_sync(0xffffffffu, mx1, 1));
        mx1 = fmaxf(mx1, __shfl_xor_sync(0xffffffffu, mx1, 2));
        float mn0 = fmaxf(m0, mx0), mn1 = fmaxf(m1, mx1);
        float s0 = __expf(m0 - mn0), s1 = __expf(m1 - mn1);
        m0 = mn0; m1 = mn1;

        float ps0 = 0.f, ps1 = 0.f;
#pragma unroll
        for (int n = 0; n < 8; n++) {
            float p0 = __expf(sc[n][0] - mn0);
            float p1 = __expf(sc[n][1] - mn0);
            float p2 = __expf(sc[n][2] - mn1);
            float p3 = __expf(sc[n][3] - mn1);
            ps0 += p0 + p1; ps1 += p2 + p3;
            sc[n][0] = p0; sc[n][1] = p1; sc[n][2] = p2; sc[n][3] = p3;
        }
        l0 = l0 * s0 + ps0;
        l1 = l1 * s1 + ps1;
#pragma unroll
        for (int n = 0; n < 8; n++) {
            acc[n][0] *= s0; acc[n][1] *= s0;
            acc[n][2] *= s1; acc[n][3] *= s1;
        }

        // ---- pack P into A fragments (hi/lo) ----
        uint32_t pfh[4][4], pfl[4][4];
#pragma unroll
        for (int kk = 0; kk < 4; kk++) {
            split_pack2(sc[2 * kk][0],     sc[2 * kk][1],     pfh[kk][0], pfl[kk][0]);
            split_pack2(sc[2 * kk][2],     sc[2 * kk][3],     pfh[kk][1], pfl[kk][1]);
            split_pack2(sc[2 * kk + 1][0], sc[2 * kk + 1][1], pfh[kk][2], pfl[kk][2]);
            split_pack2(sc[2 * kk + 1][2], sc[2 * kk + 1][3], pfh[kk][3], pfl[kk][3]);
        }

        // ---- acc += P V ----
#pragma unroll
        for (int kk = 0; kk < 4; kk++) {
            int r = kk * 16 + lrow;
#pragma unroll
            for (int g = 0; g < 4; g++) {
                uint32_t off = TILE_OFF(r, g * 2 + lsel);
                uint32_t vh0, vh1, vh2, vh3, vl0, vl1, vl2, vl3;
                ldsm4t(vh0, vh1, vh2, vh3, sv0 + off);
                ldsm4t(vl0, vl1, vl2, vl3, sv1 + off);
                mma16816(acc[2 * g],     pfh[kk], vh0, vh1);
                mma16816(acc[2 * g],     pfh[kk], vl0, vl1);
                mma16816(acc[2 * g],     pfl[kk], vh0, vh1);
                mma16816(acc[2 * g + 1], pfh[kk], vh2, vh3);
                mma16816(acc[2 * g + 1], pfh[kk], vl2, vl3);
                mma16816(acc[2 * g + 1], pfl[kk], vh2, vh3);
            }
        }
    }

    // ---- epilogue ----
    l0 += __shfl_xor_sync(0xffffffffu, l0, 1);
    l0 += __shfl_xor_sync(0xffffffffu, l0, 2);
    l1 += __shfl_xor_sync(0xffffffffu, l1, 1);
    l1 += __shfl_xor_sync(0xffffffffu, l1, 2);
    float inv0 = 1.f / l0, inv1 = 1.f / l1;

    int b = bh >> 4, h = bh & 15;
    size_t r0 = ((size_t)(b * S_LEN + qi0) * DM) + h * DH;
    size_t r1 = ((size_t)(b * S_LEN + qi1) * DM) + h * DH;
#pragma unroll
    for (int n = 0; n < 8; n++) {
        int d = n * 8 + gc2;
        uint32_t hh, ll;
        split_pack2(acc[n][0] * inv0, acc[n][1] * inv0, hh, ll);
        *(uint32_t*)(g_ahi + r0 + d) = hh;
        *(uint32_t*)(g_alo + r0 + d) = ll;
        split_pack2(acc[n][2] * inv1, acc[n][3] * inv1, hh, ll);
        *(uint32_t*)(g_ahi + r1 + d) = hh;
        *(uint32_t*)(g_alo + r1 + d) = ll;
    }
}

// ---------------------------------------------------------------------------
// Launch. Inputs: q,k,v,mask,w_q,b_q,w_k,b_k,w_v,b_v,w_o,b_o
// ---------------------------------------------------------------------------
extern "C" void kernel_launch(void* const* d_in, const int* in_sizes, int n_in,
                              void* d_out, int out_size)
{
    const float* q   = (const float*)d_in[0];
    const float* k   = (const float*)d_in[1];
    const float* v   = (const float*)d_in[2];
    const float* w_q = (const float*)d_in[4];
    const float* b_q = (const float*)d_in[5];
    const float* w_k = (const float*)d_in[6];
    const float* b_k = (const float*)d_in[7];
    const float* w_v = (const float*)d_in[8];
    const float* b_v = (const float*)d_in[9];
    const float* w_o = (const float*)d_in[10];
    const float* b_o = (const float*)d_in[11];
    float* out = (float*)d_out;

    __nv_bfloat16 *ahi, *alo, *whi, *wlo;
    __nv_bfloat16 *qhh, *qhl, *khh, *khl, *vhh, *vhl;
    cudaGetSymbolAddress((void**)&ahi, g_ahi);
    cudaGetSymbolAddress((void**)&alo, g_alo);
    cudaGetSymbolAddress((void**)&whi, g_whi);
    cudaGetSymbolAddress((void**)&wlo, g_wlo);
    cudaGetSymbolAddress((void**)&qhh, g_qhh);
    cudaGetSymbolAddress((void**)&qhl, g_qhl);
    cudaGetSymbolAddress((void**)&khh, g_khh);
    cudaGetSymbolAddress((void**)&khl, g_khl);
    cudaGetSymbolAddress((void**)&vhh, g_vhh);
    cudaGetSymbolAddress((void**)&vhl, g_vhl);

    dim3 wgrid(32, 32), wblk(32, 8);
    dim3 ggrid(8, 32),  gblk(256);
    const int n4 = M_TOT * DM / 4;

    // Q projection
    convert_w<<<wgrid, wblk>>>(w_q, whi, wlo);
    convert_act<<<(n4 + 255) / 256, 256>>>(q, ahi, alo, n4);
    gemm_mma<0><<<ggrid, gblk>>>(ahi, alo, whi, wlo, b_q, nullptr, qhh, qhl);
    // K projection
    convert_w<<<wgrid, wblk>>>(w_k, whi, wlo);
    convert_act<<<(n4 + 255) / 256, 256>>>(k, ahi, alo, n4);
    gemm_mma<0><<<ggrid, gblk>>>(ahi, alo, whi, wlo, b_k, nullptr, khh, khl);
    // V projection
    convert_w<<<wgrid, wblk>>>(w_v, whi, wlo);
    convert_act<<<(n4 + 255) / 256, 256>>>(v, ahi, alo, n4);
    gemm_mma<0><<<ggrid, gblk>>>(ahi, alo, whi, wlo, b_v, nullptr, vhh, vhl);

    // Attention (writes ctx split into g_ahi/g_alo)
    dim3 agrid(S_LEN / 64, BATCH * NHEADS);
    attn_mma<<<agrid, 128>>>();

    // Output projection
    convert_w<<<wgrid, wblk>>>(w_o, whi, wlo);
    gemm_mma<1><<<ggrid, gblk>>>(ahi, alo, whi, wlo, b_o, out, nullptr, nullptr);
}

// round 5
// speedup vs baseline: 3.5580x; 1.2783x over previous
#include <cuda_runtime.h>
#include <cuda_bf16.h>
#include <cstdint>

#define S_LEN   2048
#define DM      1024
#define NHEADS  16
#define DH      64
#define BATCH   2
#define M_TOT   (BATCH * S_LEN)                    // 4096
#define HEAD_ELEMS (BATCH * NHEADS * S_LEN * DH)   // 4194304
#define MK ((size_t)M_TOT * DM)
#define KN ((size_t)DM * DM)

// ---------------------------------------------------------------------------
// Scratch (device globals)
// slot layout: acts[0..2] = q,k,v inputs (slot 0 reused for ctx after attn)
//              weights[0..3] = w_q, w_k, w_v, w_o ; heads[0..2] = Qh,Kh,Vh
// ---------------------------------------------------------------------------
__device__ __nv_bfloat16 g_acthi[3 * M_TOT * DM];
__device__ __nv_bfloat16 g_actlo[3 * M_TOT * DM];
__device__ __nv_bfloat16 g_whi[4 * DM * DM];
__device__ __nv_bfloat16 g_wlo[4 * DM * DM];
__device__ __nv_bfloat16 g_hdhi[3 * HEAD_ELEMS];
__device__ __nv_bfloat16 g_hdlo[3 * HEAD_ELEMS];

// ---------------------------------------------------------------------------
// Helpers
// ---------------------------------------------------------------------------
__device__ __forceinline__ uint32_t smem_to_u32(const void* p) {
    uint32_t a;
    asm("{ .reg .u64 t; cvta.to.shared.u64 t, %1; cvt.u32.u64 %0, t; }"
        : "=r"(a) : "l"(p));
    return a;
}
__device__ __forceinline__ void cp_async16(uint32_t dst, const void* src) {
    asm volatile("cp.async.cg.shared.global [%0], [%1], 16;"
                 :: "r"(dst), "l"(src));
}
#define CP_COMMIT() asm volatile("cp.async.commit_group;" ::: "memory")
#define CP_WAIT0()  asm volatile("cp.async.wait_group 0;" ::: "memory")

__device__ __forceinline__ void ldsm4(uint32_t& r0, uint32_t& r1,
                                      uint32_t& r2, uint32_t& r3, uint32_t a) {
    asm volatile("ldmatrix.sync.aligned.m8n8.x4.shared.b16 {%0,%1,%2,%3}, [%4];"
                 : "=r"(r0), "=r"(r1), "=r"(r2), "=r"(r3) : "r"(a));
}
__device__ __forceinline__ void ldsm4t(uint32_t& r0, uint32_t& r1,
                                       uint32_t& r2, uint32_t& r3, uint32_t a) {
    asm volatile("ldmatrix.sync.aligned.m8n8.x4.trans.shared.b16 {%0,%1,%2,%3}, [%4];"
                 : "=r"(r0), "=r"(r1), "=r"(r2), "=r"(r3) : "r"(a));
}
__device__ __forceinline__ void mma16816(float* d, const uint32_t* a,
                                         uint32_t b0, uint32_t b1) {
    asm volatile(
        "mma.sync.aligned.m16n8k16.row.col.f32.bf16.bf16.f32 "
        "{%0,%1,%2,%3}, {%4,%5,%6,%7}, {%8,%9}, {%0,%1,%2,%3};"
        : "+f"(d[0]), "+f"(d[1]), "+f"(d[2]), "+f"(d[3])
        : "r"(a[0]), "r"(a[1]), "r"(a[2]), "r"(a[3]), "r"(b0), "r"(b1));
}
__device__ __forceinline__ void split_bf16(float x, __nv_bfloat16& hi, __nv_bfloat16& lo) {
    hi = __float2bfloat16(x);
    lo = __float2bfloat16(x - __bfloat162float(hi));
}
__device__ __forceinline__ void split_pack2(float a, float b, uint32_t& hi, uint32_t& lo) {
    __nv_bfloat162 h = __floats2bfloat162_rn(a, b);
    hi = *(uint32_t*)&h;
    float2 f = __bfloat1622float2(h);
    __nv_bfloat162 l = __floats2bfloat162_rn(a - f.x, b - f.y);
    lo = *(uint32_t*)&l;
}

// ---------------------------------------------------------------------------
// Fused conversion kernels
// ---------------------------------------------------------------------------
__global__ __launch_bounds__(256)
void convert_act_all(const float* __restrict__ q, const float* __restrict__ k,
                     const float* __restrict__ v, int n4)
{
    int i = blockIdx.x * blockDim.x + threadIdx.x;
    if (i >= n4) return;
    int z = blockIdx.z;
    const float* X = (z == 0) ? q : (z == 1) ? k : v;
    __nv_bfloat16* Xhi = g_acthi + (size_t)z * MK;
    __nv_bfloat16* Xlo = g_actlo + (size_t)z * MK;
    float4 val = ((const float4*)X)[i];
    __nv_bfloat16 h0, h1, h2, h3, l0, l1, l2, l3;
    split_bf16(val.x, h0, l0); split_bf16(val.y, h1, l1);
    split_bf16(val.z, h2, l2); split_bf16(val.w, h3, l3);
    __nv_bfloat162* ph = (__nv_bfloat162*)(Xhi + 4 * (size_t)i);
    __nv_bfloat162* pl = (__nv_bfloat162*)(Xlo + 4 * (size_t)i);
    ph[0] = __nv_bfloat162(h0, h1); ph[1] = __nv_bfloat162(h2, h3);
    pl[0] = __nv_bfloat162(l0, l1); pl[1] = __nv_bfloat162(l2, l3);
}

// fp32 W[K][N] -> transposed hi/lo bf16 Wt[N][K], 4 weights batched (z)
__global__ __launch_bounds__(256)
void convert_w_all(const float* __restrict__ w0, const float* __restrict__ w1,
                   const float* __restrict__ w2, const float* __restrict__ w3)
{
    __shared__ float t[32][33];
    int z = blockIdx.z;
    const float* W = (z == 0) ? w0 : (z == 1) ? w1 : (z == 2) ? w2 : w3;
    __nv_bfloat16* Whi = g_whi + (size_t)z * KN;
    __nv_bfloat16* Wlo = g_wlo + (size_t)z * KN;
    int bx = blockIdx.x * 32;   // n
    int by = blockIdx.y * 32;   // k
    int tx = threadIdx.x, ty = threadIdx.y;
#pragma unroll
    for (int i = ty; i < 32; i += 8)
        t[i][tx] = W[(size_t)(by + i) * DM + bx + tx];
    __syncthreads();
#pragma unroll
    for (int i = ty; i < 32; i += 8) {
        float x = t[tx][i];
        __nv_bfloat16 h, l; split_bf16(x, h, l);
        size_t o = (size_t)(bx + i) * DM + by + tx;
        Whi[o] = h; Wlo[o] = l;
    }
}

// ---------------------------------------------------------------------------
// Split-bf16 GEMM, cp.async 2-stage pipeline. Tile 128x128, BK=32, 8 warps.
// MODE 0: batched QKV (grid.z=3), dst = head-split bf16 hi/lo [B,H,S,Dh]
// MODE 1: output projection, dst = plain fp32 [M,N]
// ---------------------------------------------------------------------------
#define TP 80
#define ARR_BYTES   (128 * TP)            // 10240
#define STAGE_BYTES (4 * ARR_BYTES)       // 40960
#define GEMM_SMEM   (2 * STAGE_BYTES)     // 81920

template <int MODE>
__global__ __launch_bounds__(256)
void gemm_mma(const float* __restrict__ bias0, const float* __restrict__ bias1,
              const float* __restrict__ bias2, float* __restrict__ dstF)
{
    extern __shared__ __align__(128) uint8_t dsm[];

    const int tid   = threadIdx.x;
    const int wid   = tid >> 5;
    const int lane  = tid & 31;
    const int warpM = wid & 3;
    const int warpN = wid >> 2;
    const int bn    = blockIdx.x;
    const int bm    = blockIdx.y;
    const int z     = blockIdx.z;

    const __nv_bfloat16 *Ahi, *Alo, *Whi, *Wlo;
    const float* bias;
    __nv_bfloat16 *dstHi = nullptr, *dstLo = nullptr;
    if (MODE == 0) {
        Ahi = g_acthi + (size_t)z * MK;  Alo = g_actlo + (size_t)z * MK;
        Whi = g_whi   + (size_t)z * KN;  Wlo = g_wlo   + (size_t)z * KN;
        bias = (z == 0) ? bias0 : (z == 1) ? bias1 : bias2;
        dstHi = g_hdhi + (size_t)z * HEAD_ELEMS;
        dstLo = g_hdlo + (size_t)z * HEAD_ELEMS;
    } else {
        Ahi = g_acthi;  Alo = g_actlo;
        Whi = g_whi + 3 * KN;  Wlo = g_wlo + 3 * KN;
        bias = bias0;
    }

    const __nv_bfloat16* gA0 = Ahi + (size_t)bm * 128 * DM;
    const __nv_bfloat16* gA1 = Alo + (size_t)bm * 128 * DM;
    const __nv_bfloat16* gB0 = Whi + (size_t)bn * 128 * DM;
    const __nv_bfloat16* gB1 = Wlo + (size_t)bn * 128 * DM;

    const uint32_t sbase = smem_to_u32(dsm);
    const int ldr = tid >> 2;            // 0..63 (x2 via second pass)
    const int ldc = tid & 3;

    // prologue: stage 0
    {
#pragma unroll
        for (int t = 0; t < 2; t++) {
            int r = ldr + t * 64;
            uint32_t so = (uint32_t)(r * TP + ldc * 16);
            size_t go = (size_t)r * DM + ldc * 8;
            cp_async16(sbase + so,                 gA0 + go);
            cp_async16(sbase + ARR_BYTES + so,     gA1 + go);
            cp_async16(sbase + 2 * ARR_BYTES + so, gB0 + go);
            cp_async16(sbase + 3 * ARR_BYTES + so, gB1 + go);
        }
        CP_COMMIT();
    }

    float acc[2][8][4];
#pragma unroll
    for (int i = 0; i < 2; i++)
#pragma unroll
        for (int j = 0; j < 8; j++)
#pragma unroll
            for (int c = 0; c < 4; c++) acc[i][j][c] = 0.f;

    const int lrow = lane & 15;
    const int lcol = (lane >> 4) * 16;

    for (int it = 0; it < DM / 32; it++) {
        CP_WAIT0();
        __syncthreads();
        if (it + 1 < DM / 32) {
            uint32_t sb = sbase + ((it + 1) & 1) * STAGE_BYTES;
            int kt = (it + 1) * 32;
#pragma unroll
            for (int t = 0; t < 2; t++) {
                int r = ldr + t * 64;
                uint32_t so = (uint32_t)(r * TP + ldc * 16);
                size_t go = (size_t)r * DM + kt + ldc * 8;
                cp_async16(sb + so,                 gA0 + go);
                cp_async16(sb + ARR_BYTES + so,     gA1 + go);
                cp_async16(sb + 2 * ARR_BYTES + so, gB0 + go);
                cp_async16(sb + 3 * ARR_BYTES + so, gB1 + go);
            }
            CP_COMMIT();
        }

        const uint32_t st = sbase + (it & 1) * STAGE_BYTES;
        const uint32_t sA0 = st, sA1 = st + ARR_BYTES;
        const uint32_t sB0 = st + 2 * ARR_BYTES, sB1 = st + 3 * ARR_BYTES;

#pragma unroll
        for (int kk = 0; kk < 2; kk++) {
            uint32_t ah[2][4], al[2][4];
#pragma unroll
            for (int mt = 0; mt < 2; mt++) {
                uint32_t off = (uint32_t)((warpM * 32 + mt * 16 + lrow) * TP
                                          + kk * 32 + lcol);
                ldsm4(ah[mt][0], ah[mt][1], ah[mt][2], ah[mt][3], sA0 + off);
                ldsm4(al[mt][0], al[mt][1], al[mt][2], al[mt][3], sA1 + off);
            }
#pragma unroll
            for (int np = 0; np < 4; np++) {
                uint32_t off = (uint32_t)((warpN * 64 + np * 16 + lrow) * TP
                                          + kk * 32 + lcol);
                uint32_t bh0, bh1, bh2, bh3, bl0, bl1, bl2, bl3;
                ldsm4(bh0, bh1, bh2, bh3, sB0 + off);
                ldsm4(bl0, bl1, bl2, bl3, sB1 + off);
#pragma unroll
                for (int mt = 0; mt < 2; mt++) {
                    mma16816(acc[mt][2 * np],     ah[mt], bh0, bh2);
                    mma16816(acc[mt][2 * np],     ah[mt], bl0, bl2);
                    mma16816(acc[mt][2 * np],     al[mt], bh0, bh2);
                    mma16816(acc[mt][2 * np + 1], ah[mt], bh1, bh3);
                    mma16816(acc[mt][2 * np + 1], ah[mt], bl1, bl3);
                    mma16816(acc[mt][2 * np + 1], al[mt], bh1, bh3);
                }
            }
        }
        __syncthreads();
    }

    // epilogue
    const int qr = lane >> 2;
    const int qc = (lane & 3) * 2;
#pragma unroll
    for (int nt = 0; nt < 8; nt++) {
        int n = bn * 128 + warpN * 64 + nt * 8 + qc;
        float2 bb = *(const float2*)(bias + n);
#pragma unroll
        for (int mt = 0; mt < 2; mt++) {
            int m0 = bm * 128 + warpM * 32 + mt * 16 + qr;
            float v00 = acc[mt][nt][0] + bb.x, v01 = acc[mt][nt][1] + bb.y;
            float v10 = acc[mt][nt][2] + bb.x, v11 = acc[mt][nt][3] + bb.y;
            if (MODE == 1) {
                *(float2*)(dstF + (size_t)m0 * DM + n)       = make_float2(v00, v01);
                *(float2*)(dstF + (size_t)(m0 + 8) * DM + n) = make_float2(v10, v11);
            } else {
                int h = n >> 6, d = n & 63;
                int b0 = m0 >> 11, s0 = m0 & 2047;
                int m1 = m0 + 8;
                int b1 = m1 >> 11, s1 = m1 & 2047;
                size_t o0 = ((size_t)(b0 * NHEADS + h) * S_LEN + s0) * DH + d;
                size_t o1 = ((size_t)(b1 * NHEADS + h) * S_LEN + s1) * DH + d;
                uint32_t h2, l2;
                split_pack2(v00, v01, h2, l2);
                *(uint32_t*)(dstHi + o0) = h2; *(uint32_t*)(dstLo + o0) = l2;
                split_pack2(v10, v11, h2, l2);
                *(uint32_t*)(dstHi + o1) = h2; *(uint32_t*)(dstLo + o1) = l2;
            }
        }
    }
}

// ---------------------------------------------------------------------------
// Tensor-core causal flash attention with cp.async double-buffered K/V.
// grid = (32 qtiles, 32 bh), block = 128 (4 warps).
// smem: Q hi/lo (16KB) + 2 stages x (Khi,Klo,Vhi,Vlo) (64KB) = 80KB dynamic.
// ---------------------------------------------------------------------------
#define TILE_OFF(r, c) ((uint32_t)((r) * 128 + (((c) ^ ((r) & 7)) << 4)))
#define ATT_SMEM (16384 + 2 * 32768)

__global__ __launch_bounds__(128)
void attn_mma()
{
    extern __shared__ __align__(128) uint8_t dsm[];
    const uint32_t sbase = smem_to_u32(dsm);
    const uint32_t sq0 = sbase, sq1 = sbase + 8192;
    const uint32_t kvb = sbase + 16384;

    const int tid  = threadIdx.x;
    const int wid  = tid >> 5;
    const int lane = tid & 31;
    const int bh   = blockIdx.y;
    const int qt   = gridDim.x - 1 - blockIdx.x;   // heavy tiles first
    const int q0   = qt * 64;
    const int T    = qt + 1;

    const size_t hb = (size_t)bh * S_LEN * DH;
    const __nv_bfloat16* Qh = g_hdhi + hb;
    const __nv_bfloat16* Ql = g_hdlo + hb;
    const __nv_bfloat16* Kh = g_hdhi + HEAD_ELEMS + hb;
    const __nv_bfloat16* Kl = g_hdlo + HEAD_ELEMS + hb;
    const __nv_bfloat16* Vh = g_hdhi + 2 * (size_t)HEAD_ELEMS + hb;
    const __nv_bfloat16* Vl = g_hdlo + 2 * (size_t)HEAD_ELEMS + hb;

    // prologue: stage Q + first K/V tile
#pragma unroll
    for (int it = 0; it < 4; it++) {
        int id = tid + it * 128;
        int r  = id >> 3;
        int c  = id & 7;
        uint32_t so = TILE_OFF(r, c);
        size_t  gq = (size_t)(q0 + r) * DH + c * 8;
        size_t  gk = (size_t)r * DH + c * 8;
        cp_async16(sq0 + so, Qh + gq);
        cp_async16(sq1 + so, Ql + gq);
        cp_async16(kvb + so,         Kh + gk);
        cp_async16(kvb + 8192 + so,  Kl + gk);
        cp_async16(kvb + 16384 + so, Vh + gk);
        cp_async16(kvb + 24576 + so, Vl + gk);
    }
    CP_COMMIT();

    const int lrow = lane & 15;
    const int lsel = lane >> 4;
    uint32_t qfh[4][4], qfl[4][4];

    float m0 = -1e30f, m1 = -1e30f, l0 = 0.f, l1 = 0.f;
    float acc[8][4];
#pragma unroll
    for (int n = 0; n < 8; n++)
#pragma unroll
        for (int c = 0; c < 4; c++) acc[n][c] = 0.f;

    const int gr  = lane >> 2;
    const int gc2 = (lane & 3) * 2;
    const int qi0 = q0 + wid * 16 + gr;
    const int qi1 = qi0 + 8;

    for (int t = 0; t < T; t++) {
        CP_WAIT0();
        __syncthreads();
        if (t + 1 < T) {
            uint32_t sb = kvb + ((t + 1) & 1) * 32768;
            int k0n = (t + 1) * 64;
#pragma unroll
            for (int it = 0; it < 4; it++) {
                int id = tid + it * 128;
                int r  = id >> 3;
                int c  = id & 7;
                uint32_t so = TILE_OFF(r, c);
                size_t  gk = (size_t)(k0n + r) * DH + c * 8;
                cp_async16(sb + so,         Kh + gk);
                cp_async16(sb + 8192 + so,  Kl + gk);
                cp_async16(sb + 16384 + so, Vh + gk);
                cp_async16(sb + 24576 + so, Vl + gk);
            }
            CP_COMMIT();
        }
        if (t == 0) {
            int r = wid * 16 + lrow;
#pragma unroll
            for (int ks = 0; ks < 4; ks++) {
                uint32_t off = TILE_OFF(r, ks * 2 + lsel);
                ldsm4(qfh[ks][0], qfh[ks][1], qfh[ks][2], qfh[ks][3], sq0 + off);
                ldsm4(qfl[ks][0], qfl[ks][1], qfl[ks][2], qfl[ks][3], sq1 + off);
            }
        }

        const uint32_t st = kvb + (t & 1) * 32768;
        const uint32_t sk0 = st, sk1 = st + 8192;
        const uint32_t sv0 = st + 16384, sv1 = st + 24576;
        const int k0 = t * 64;

        // scores
        float sc[8][4];
#pragma unroll
        for (int n = 0; n < 8; n++)
#pragma unroll
            for (int c = 0; c < 4; c++) sc[n][c] = 0.f;

#pragma unroll
        for (int np = 0; np < 4; np++) {
            int r = np * 16 + lrow;
#pragma unroll
            for (int ks = 0; ks < 4; ks++) {
                uint32_t off = TILE_OFF(r, ks * 2 + lsel);
                uint32_t kh0, kh1, kh2, kh3, kl0, kl1, kl2, kl3;
                ldsm4(kh0, kh1, kh2, kh3, sk0 + off);
                ldsm4(kl0, kl1, kl2, kl3, sk1 + off);
                mma16816(sc[2 * np],     qfh[ks], kh0, kh2);
                mma16816(sc[2 * np],     qfh[ks], kl0, kl2);
                mma16816(sc[2 * np],     qfl[ks], kh0, kh2);
                mma16816(sc[2 * np + 1], qfh[ks], kh1, kh3);
                mma16816(sc[2 * np + 1], qfh[ks], kl1, kl3);
                mma16816(sc[2 * np + 1], qfl[ks], kh1, kh3);
            }
        }

        // scale + causal mask
#pragma unroll
        for (int n = 0; n < 8; n++) {
            int cb = k0 + n * 8 + gc2;
#pragma unroll
            for (int c = 0; c < 4; c++) {
                int col = cb + (c & 1);
                int row = (c < 2) ? qi0 : qi1;
                float v = sc[n][c] * 0.125f;
                sc[n][c] = (col <= row) ? v : -1e30f;
            }
        }

        // online softmax
        float mx0 = -1e30f, mx1 = -1e30f;
#pragma unroll
        for (int n = 0; n < 8; n++) {
            mx0 = fmaxf(mx0, fmaxf(sc[n][0], sc[n][1]));
            mx1 = fmaxf(mx1, fmaxf(sc[n][2], sc[n][3]));
        }
        mx0 = fmaxf(mx0, __shfl_xor_sync(0xffffffffu, mx0, 1));
        mx0 = fmaxf(mx0, __shfl_xor_sync(0xffffffffu, mx0, 2));
        mx1 = fmaxf(mx1, __shfl_xor_sync(0xffffffffu, mx1, 1));
        mx1 = fmaxf(mx1, __shfl_xor_sync(0xffffffffu, mx1, 2));
        float mn0 = fmaxf(m0, mx0), mn1 = fmaxf(m1, mx1);
        float s0 = __expf(m0 - mn0), s1 = __expf(m1 - mn1);
        m0 = mn0; m1 = mn1;

        float ps0 = 0.f, ps1 = 0.f;
#pragma unroll
        for (int n = 0; n < 8; n++) {
            float p0 = __expf(sc[n][0] - mn0);
            float p1 = __expf(sc[n][1] - mn0);
            float p2 = __expf(sc[n][2] - mn1);
            float p3 = __expf(sc[n][3] - mn1);
            ps0 += p0 + p1; ps1 += p2 + p3;
            sc[n][0] = p0; sc[n][1] = p1; sc[n][2] = p2; sc[n][3] = p3;
        }
        l0 = l0 * s0 + ps0;
        l1 = l1 * s1 + ps1;
#pragma unroll
        for (int n = 0; n < 8; n++) {
            acc[n][0] *= s0; acc[n][1] *= s0;
            acc[n][2] *= s1; acc[n][3] *= s1;
        }

        // pack P into A fragments
        uint32_t pfh[4][4], pfl[4][4];
#pragma unroll
        for (int kk = 0; kk < 4; kk++) {
            split_pack2(sc[2 * kk][0],     sc[2 * kk][1],     pfh[kk][0], pfl[kk][0]);
            split_pack2(sc[2 * kk][2],     sc[2 * kk][3],     pfh[kk][1], pfl[kk][1]);
            split_pack2(sc[2 * kk + 1][0], sc[2 * kk + 1][1], pfh[kk][2], pfl[kk][2]);
            split_pack2(sc[2 * kk + 1][2], sc[2 * kk + 1][3], pfh[kk][3], pfl[kk][3]);
        }

        // acc += P V
#pragma unroll
        for (int kk = 0; kk < 4; kk++) {
            int r = kk * 16 + lrow;
#pragma unroll
            for (int g = 0; g < 4; g++) {
                uint32_t off = TILE_OFF(r, g * 2 + lsel);
                uint32_t vh0, vh1, vh2, vh3, vl0, vl1, vl2, vl3;
                ldsm4t(vh0, vh1, vh2, vh3, sv0 + off);
                ldsm4t(vl0, vl1, vl2, vl3, sv1 + off);
                mma16816(acc[2 * g],     pfh[kk], vh0, vh1);
                mma16816(acc[2 * g],     pfh[kk], vl0, vl1);
                mma16816(acc[2 * g],     pfl[kk], vh0, vh1);
                mma16816(acc[2 * g + 1], pfh[kk], vh2, vh3);
                mma16816(acc[2 * g + 1], pfh[kk], vl2, vl3);
                mma16816(acc[2 * g + 1], pfl[kk], vh2, vh3);
            }
        }
        __syncthreads();
    }

    // epilogue -> ctx split into act slot 0
    l0 += __shfl_xor_sync(0xffffffffu, l0, 1);
    l0 += __shfl_xor_sync(0xffffffffu, l0, 2);
    l1 += __shfl_xor_sync(0xffffffffu, l1, 1);
    l1 += __shfl_xor_sync(0xffffffffu, l1, 2);
    float inv0 = 1.f / l0, inv1 = 1.f / l1;

    int b = bh >> 4, h = bh & 15;
    size_t r0 = ((size_t)(b * S_LEN + qi0) * DM) + h * DH;
    size_t r1 = ((size_t)(b * S_LEN + qi1) * DM) + h * DH;
#pragma unroll
    for (int n = 0; n < 8; n++) {
        int d = n * 8 + gc2;
        uint32_t hh, ll;
        split_pack2(acc[n][0] * inv0, acc[n][1] * inv0, hh, ll);
        *(uint32_t*)(g_acthi + r0 + d) = hh;
        *(uint32_t*)(g_actlo + r0 + d) = ll;
        split_pack2(acc[n][2] * inv1, acc[n][3] * inv1, hh, ll);
        *(uint32_t*)(g_acthi + r1 + d) = hh;
        *(uint32_t*)(g_actlo + r1 + d) = ll;
    }
}

// ---------------------------------------------------------------------------
// Launch. Inputs: q,k,v,mask,w_q,b_q,w_k,b_k,w_v,b_v,w_o,b_o
// ---------------------------------------------------------------------------
extern "C" void kernel_launch(void* const* d_in, const int* in_sizes, int n_in,
                              void* d_out, int out_size)
{
    const float* q   = (const float*)d_in[0];
    const float* k   = (const float*)d_in[1];
    const float* v   = (const float*)d_in[2];
    const float* w_q = (const float*)d_in[4];
    const float* b_q = (const float*)d_in[5];
    const float* w_k = (const float*)d_in[6];
    const float* b_k = (const float*)d_in[7];
    const float* w_v = (const float*)d_in[8];
    const float* b_v = (const float*)d_in[9];
    const float* w_o = (const float*)d_in[10];
    const float* b_o = (const float*)d_in[11];
    float* out = (float*)d_out;

    static bool attr_done = false;
    if (!attr_done) {
        cudaFuncSetAttribute(gemm_mma<0>, cudaFuncAttributeMaxDynamicSharedMemorySize,
                             GEMM_SMEM);
        cudaFuncSetAttribute(gemm_mma<1>, cudaFuncAttributeMaxDynamicSharedMemorySize,
                             GEMM_SMEM);
        cudaFuncSetAttribute(attn_mma, cudaFuncAttributeMaxDynamicSharedMemorySize,
                             ATT_SMEM);
        attr_done = true;
    }

    const int n4 = M_TOT * DM / 4;

    // 1. all weight conversions (4 weights)
    convert_w_all<<<dim3(32, 32, 4), dim3(32, 8)>>>(w_q, w_k, w_v, w_o);
    // 2. all activation conversions (q,k,v)
    convert_act_all<<<dim3((n4 + 255) / 256, 1, 3), 256>>>(q, k, v, n4);
    // 3. batched QKV projections
    gemm_mma<0><<<dim3(8, 32, 3), 256, GEMM_SMEM>>>(b_q, b_k, b_v, nullptr);
    // 4. attention
    attn_mma<<<dim3(S_LEN / 64, BATCH * NHEADS), 128, ATT_SMEM>>>();
    // 5. output projection
    gemm_mma<1><<<dim3(8, 32, 1), 256, GEMM_SMEM>>>(b_o, nullptr, nullptr, out);
}